// round 4
// baseline (speedup 1.0000x reference)
#include <cuda_runtime.h>
#include <math.h>

#define BB 256
#define N_SV 64
#define N_TRK 512
#define N_PFC 512
#define KNN 8
#define HH 32
#define CAP 6    // per-dst candidate buffer slots (u64 each)

typedef unsigned long long u64;

// ---------------- scratch (static device arrays; no allocation) -------------
__device__ float g_sv [BB * N_SV  * HH];
__device__ float g_trk[BB * N_TRK * HH];
__device__ float g_pfc[BB * N_PFC * HH];
__device__ float g_U  [BB * N_TRK * HH];
__device__ float g_V  [BB * N_PFC * HH];
__device__ float g_V1 [BB * N_SV  * HH];
__device__ float g_f1 [BB * N_TRK * HH];
__device__ float g_f2 [BB * N_TRK * HH];
__device__ float g_f3 [BB * N_TRK * HH];

__device__ __forceinline__ float eluf(float x) {
    return x > 0.f ? x : (expf(x) - 1.f);
}

// ================= fused encoder: 2-layer MLP, 4 nodes per warp =============
template <int FIN>
__device__ __forceinline__ void encode_body(
    const float* __restrict__ x,
    const float* __restrict__ W1, const float* __restrict__ b1,
    const float* __restrict__ W2, const float* __restrict__ b2,
    float* __restrict__ out, int blk,
    float* w1s, float* w2s, float* b1s, float* b2s)
{
    int tid = threadIdx.x;
    for (int i = tid; i < FIN * 32; i += 256) w1s[i] = W1[i];
    for (int i = tid; i < 1024;     i += 256) w2s[i] = W2[i];
    if (tid < 32) { b1s[tid] = b1[tid]; b2s[tid] = b2[tid]; }
    __syncthreads();

    int lane = tid & 31, wid = tid >> 5;
    int nb = blk * 32 + wid * 4;

    float xv0 = (lane < FIN) ? x[(size_t)(nb + 0) * FIN + lane] : 0.f;
    float xv1 = (lane < FIN) ? x[(size_t)(nb + 1) * FIN + lane] : 0.f;
    float xv2 = (lane < FIN) ? x[(size_t)(nb + 2) * FIN + lane] : 0.f;
    float xv3 = (lane < FIN) ? x[(size_t)(nb + 3) * FIN + lane] : 0.f;

    float h0 = b1s[lane], h1 = h0, h2 = h0, h3 = h0;
#pragma unroll
    for (int i = 0; i < FIN; ++i) {
        float w = w1s[i * 32 + lane];
        h0 = fmaf(__shfl_sync(0xffffffffu, xv0, i), w, h0);
        h1 = fmaf(__shfl_sync(0xffffffffu, xv1, i), w, h1);
        h2 = fmaf(__shfl_sync(0xffffffffu, xv2, i), w, h2);
        h3 = fmaf(__shfl_sync(0xffffffffu, xv3, i), w, h3);
    }
    h0 = eluf(h0); h1 = eluf(h1); h2 = eluf(h2); h3 = eluf(h3);

    float o0 = b2s[lane], o1 = o0, o2 = o0, o3 = o0;
#pragma unroll
    for (int i = 0; i < 32; ++i) {
        float w = w2s[i * 32 + lane];
        o0 = fmaf(__shfl_sync(0xffffffffu, h0, i), w, o0);
        o1 = fmaf(__shfl_sync(0xffffffffu, h1, i), w, o1);
        o2 = fmaf(__shfl_sync(0xffffffffu, h2, i), w, o2);
        o3 = fmaf(__shfl_sync(0xffffffffu, h3, i), w, o3);
    }
    out[(size_t)(nb + 0) * 32 + lane] = eluf(o0);
    out[(size_t)(nb + 1) * 32 + lane] = eluf(o1);
    out[(size_t)(nb + 2) * 32 + lane] = eluf(o2);
    out[(size_t)(nb + 3) * 32 + lane] = eluf(o3);
}

__global__ void __launch_bounds__(256) encode_all_k(
    const float* x_sv, const float* x_trk, const float* x_pfc,
    const float* svW1, const float* svb1, const float* svW2, const float* svb2,
    const float* tkW1, const float* tkb1, const float* tkW2, const float* tkb2,
    const float* pfW1, const float* pfb1, const float* pfW2, const float* pfb2,
    float* o_sv, float* o_trk, float* o_pfc)
{
    __shared__ float w1s[32 * 32];
    __shared__ float w2s[32 * 32];
    __shared__ float b1s[32], b2s[32];
    int b = blockIdx.x;
    if (b < 512)
        encode_body<14>(x_sv, svW1, svb1, svW2, svb2, o_sv, b, w1s, w2s, b1s, b2s);
    else if (b < 4608)
        encode_body<30>(x_trk, tkW1, tkb1, tkW2, tkb2, o_trk, b - 512, w1s, w2s, b1s, b2s);
    else
        encode_body<10>(x_pfc, pfW1, pfb1, pfW2, pfb2, o_pfc, b - 4608, w1s, w2s, b1s, b2s);
}

// ================ fused 32x32 linear (mode 0: (Wa-Wb)+b, mode 1: Wb) ========
__device__ __forceinline__ void lin_body(
    const float* __restrict__ in, float* __restrict__ out, int blk, int mode,
    const float* __restrict__ convW, const float* __restrict__ convB,
    float* ws, float* bs)
{
    int tid = threadIdx.x;
    for (int i = tid; i < 1024; i += 256)
        ws[i] = (mode == 0) ? (convW[i] - convW[1024 + i]) : convW[1024 + i];
    if (tid < 32) bs[tid] = (mode == 0) ? convB[tid] : 0.f;
    __syncthreads();

    int lane = tid & 31, wid = tid >> 5;
    int nb = blk * 32 + wid * 4;

    float xv0 = in[(size_t)(nb + 0) * 32 + lane];
    float xv1 = in[(size_t)(nb + 1) * 32 + lane];
    float xv2 = in[(size_t)(nb + 2) * 32 + lane];
    float xv3 = in[(size_t)(nb + 3) * 32 + lane];
    float o0 = bs[lane], o1 = o0, o2 = o0, o3 = o0;
#pragma unroll
    for (int i = 0; i < 32; ++i) {
        float w = ws[i * 32 + lane];
        o0 = fmaf(__shfl_sync(0xffffffffu, xv0, i), w, o0);
        o1 = fmaf(__shfl_sync(0xffffffffu, xv1, i), w, o1);
        o2 = fmaf(__shfl_sync(0xffffffffu, xv2, i), w, o2);
        o3 = fmaf(__shfl_sync(0xffffffffu, xv3, i), w, o3);
    }
    out[(size_t)(nb + 0) * 32 + lane] = o0;
    out[(size_t)(nb + 1) * 32 + lane] = o1;
    out[(size_t)(nb + 2) * 32 + lane] = o2;
    out[(size_t)(nb + 3) * 32 + lane] = o3;
}

__global__ void __launch_bounds__(256) lin_all_k(
    const float* sv, const float* trk, const float* pfc,
    float* V1, float* U, float* V,
    const float* convW, const float* convB)
{
    __shared__ float ws[1024];
    __shared__ float bs[32];
    int b = blockIdx.x;
    if (b < 512)        lin_body(sv,  V1, b,        1, convW, convB, ws, bs);
    else if (b < 4608)  lin_body(trk, U,  b - 512,  0, convW, convB, ws, bs);
    else                lin_body(pfc, V,  b - 4608, 1, convW, convB, ws, bs);
}

__global__ void __launch_bounds__(256) lin2_k(
    const float* f1, const float* f2, float* V, float* U,
    const float* convW, const float* convB)
{
    __shared__ float ws[1024];
    __shared__ float bs[32];
    int b = blockIdx.x;
    if (b < 4096) lin_body(f1, V, b,        1, convW, convB, ws, bs);
    else          lin_body(f2, U, b - 4096, 0, convW, convB, ws, bs);
}

// ================= kNN + max aggregation ====================================
// Candidates packed as u64: (f32 bits of true d2 << 32) | src_index.
// d2 >= 0 so float-bit order == uint order; low bits make all candidates
// distinct -> strict '<' selection is exact, ties resolve to lower index.
__device__ __forceinline__ void flush_u64(const u64* mybuf, int& cnt, u64 (&dist)[KNN])
{
    for (int i = 0; i < cnt; ++i) {
        u64 c = mybuf[i];
        if (c < dist[KNN - 1]) {
            dist[KNN - 1] = c;
#pragma unroll
            for (int p = KNN - 1; p > 0; --p) {
                if (dist[p] < dist[p - 1]) {
                    u64 t = dist[p]; dist[p] = dist[p - 1]; dist[p - 1] = t;
                }
            }
        }
    }
    cnt = 0;
}

__global__ void __launch_bounds__(256, 2) knn_k(
                      const float* __restrict__ src_enc,
                      const float* __restrict__ dst_enc,
                      const float* __restrict__ V,
                      const float* __restrict__ U,
                      float* __restrict__ out, int Ns)
{
    extern __shared__ float sm[];
    float* srcf = sm;                          // Ns*32
    float* sq   = sm + Ns * 32;                // Ns
    int*   idxs = (int*)(sq + Ns);             // 512*8
    u64*   buf  = (u64*)(idxs + 512 * KNN);    // 512*CAP u64

    int tid  = threadIdx.x;
    int lane = tid & 31;
    int wid  = tid >> 5;
    int e    = blockIdx.x;

    {   // stage src features (float4)
        const float4* sb4 = reinterpret_cast<const float4*>(src_enc + (size_t)e * Ns * 32);
        float4* sf4 = reinterpret_cast<float4*>(srcf);
        for (int i = tid; i < Ns * 8; i += 256) sf4[i] = sb4[i];
    }
    __syncthreads();

    for (int r = wid; r < Ns; r += 8) {
        float v = srcf[r * 32 + lane];
        v *= v;
#pragma unroll
        for (int o = 16; o; o >>= 1) v += __shfl_down_sync(0xffffffffu, v, o);
        if (lane == 0) sq[r] = v;
    }
    __syncthreads();

    // ---- load both dst rows: xi = -2*dst packed f32x2; sd = ||dst||^2 ----
    u64 xi0[16], xi1[16];
    float sd0 = 0.f, sd1 = 0.f;
    {
        const float4* d0 = reinterpret_cast<const float4*>(dst_enc + ((size_t)e * 512 + tid) * 32);
        const float4* d1 = reinterpret_cast<const float4*>(dst_enc + ((size_t)e * 512 + tid + 256) * 32);
#pragma unroll
        for (int q = 0; q < 8; ++q) {
            float4 v = d0[q];
            sd0 = fmaf(v.x, v.x, sd0); sd0 = fmaf(v.y, v.y, sd0);
            sd0 = fmaf(v.z, v.z, sd0); sd0 = fmaf(v.w, v.w, sd0);
            float a = -2.f * v.x, b = -2.f * v.y, c = -2.f * v.z, d = -2.f * v.w;
            asm("mov.b64 %0, {%1, %2};" : "=l"(xi0[2 * q + 0]) : "f"(a), "f"(b));
            asm("mov.b64 %0, {%1, %2};" : "=l"(xi0[2 * q + 1]) : "f"(c), "f"(d));
            v = d1[q];
            sd1 = fmaf(v.x, v.x, sd1); sd1 = fmaf(v.y, v.y, sd1);
            sd1 = fmaf(v.z, v.z, sd1); sd1 = fmaf(v.w, v.w, sd1);
            a = -2.f * v.x; b = -2.f * v.y; c = -2.f * v.z; d = -2.f * v.w;
            asm("mov.b64 %0, {%1, %2};" : "=l"(xi1[2 * q + 0]) : "f"(a), "f"(b));
            asm("mov.b64 %0, {%1, %2};" : "=l"(xi1[2 * q + 1]) : "f"(c), "f"(d));
        }
    }

    u64 dist0[KNN], dist1[KNN];
#pragma unroll
    for (int k = 0; k < KNN; ++k) { dist0[k] = ~0ull; dist1[k] = ~0ull; }

    int cnt0 = 0, cnt1 = 0;
    unsigned src_sa  = (unsigned)__cvta_generic_to_shared(srcf);
    u64* mybuf0 = buf + tid * 2 * CAP;
    u64* mybuf1 = mybuf0 + CAP;
    unsigned buf0_sa = (unsigned)__cvta_generic_to_shared(mybuf0);
    unsigned buf1_sa = (unsigned)__cvta_generic_to_shared(mybuf1);

    for (int s0 = 0; s0 < Ns; s0 += 4) {
#pragma unroll
        for (int j = 0; j < 4; ++j) {
            int s = s0 + j;
            unsigned addr = src_sa + (unsigned)s * 128u;
            u64 a0 = 0ull, a1 = 0ull, b0 = 0ull, b1 = 0ull;
#pragma unroll
            for (int q = 0; q < 8; ++q) {
                u64 p0, p1;
                asm("ld.shared.v2.b64 {%0,%1},[%2];"
                    : "=l"(p0), "=l"(p1) : "r"(addr + q * 16u));
                asm("fma.rn.f32x2 %0, %1, %2, %0;" : "+l"(a0) : "l"(xi0[2 * q + 0]), "l"(p0));
                asm("fma.rn.f32x2 %0, %1, %2, %0;" : "+l"(b0) : "l"(xi1[2 * q + 0]), "l"(p0));
                asm("fma.rn.f32x2 %0, %1, %2, %0;" : "+l"(a1) : "l"(xi0[2 * q + 1]), "l"(p1));
                asm("fma.rn.f32x2 %0, %1, %2, %0;" : "+l"(b1) : "l"(xi1[2 * q + 1]), "l"(p1));
            }
            float sqs = sq[s];
            float l0, h0, l1, h1;
            asm("mov.b64 {%0,%1}, %2;" : "=f"(l0), "=f"(h0) : "l"(a0));
            asm("mov.b64 {%0,%1}, %2;" : "=f"(l1), "=f"(h1) : "l"(a1));
            float sc0 = fmaxf((sqs + sd0) + ((l0 + h0) + (l1 + h1)), 0.f);
            asm("mov.b64 {%0,%1}, %2;" : "=f"(l0), "=f"(h0) : "l"(b0));
            asm("mov.b64 {%0,%1}, %2;" : "=f"(l1), "=f"(h1) : "l"(b1));
            float sc1 = fmaxf((sqs + sd1) + ((l0 + h0) + (l1 + h1)), 0.f);

            u64 c0 = ((u64)__float_as_uint(sc0) << 32) | (unsigned)s;
            u64 c1 = ((u64)__float_as_uint(sc1) << 32) | (unsigned)s;
            asm volatile(
                "{.reg .pred p; setp.lt.u64 p, %1, %2; @p st.shared.b64 [%0], %1;}"
                :: "r"(buf0_sa + (unsigned)cnt0 * 8u), "l"(c0), "l"(dist0[KNN - 1])
                : "memory");
            cnt0 += (c0 < dist0[KNN - 1]) ? 1 : 0;
            asm volatile(
                "{.reg .pred p; setp.lt.u64 p, %1, %2; @p st.shared.b64 [%0], %1;}"
                :: "r"(buf1_sa + (unsigned)cnt1 * 8u), "l"(c1), "l"(dist1[KNN - 1])
                : "memory");
            cnt1 += (c1 < dist1[KNN - 1]) ? 1 : 0;
        }
        int mc = (cnt0 > cnt1) ? cnt0 : cnt1;
        if (__any_sync(0xffffffffu, mc >= 3)) {
            flush_u64(mybuf0, cnt0, dist0);
            flush_u64(mybuf1, cnt1, dist1);
        }
    }
    flush_u64(mybuf0, cnt0, dist0);
    flush_u64(mybuf1, cnt1, dist1);

#pragma unroll
    for (int k = 0; k < KNN; ++k) {
        idxs[tid * KNN + k]         = (int)(unsigned)dist0[k];
        idxs[(tid + 256) * KNN + k] = (int)(unsigned)dist1[k];
    }
    __syncthreads();

    // ---- phase 3: warp-per-dst aggregation (coalesced V gathers) ----
    const float* Ve = V + (size_t)e * Ns * 32;
    for (int dd = wid; dd < 512; dd += 8) {
        int dg = e * 512 + dd;
        float m = -3.4e38f;
#pragma unroll
        for (int k = 0; k < KNN; ++k) {
            int s = idxs[dd * KNN + k];
            m = fmaxf(m, Ve[s * 32 + lane]);
        }
        out[(size_t)dg * 32 + lane] = eluf(U[(size_t)dg * 32 + lane] + m);
    }
}

// ---------------- mean pool + head MLP + sigmoid -----------------------------
__global__ void pool_k(const float* __restrict__ f3,
                       const float* __restrict__ W1, const float* __restrict__ b1,
                       const float* __restrict__ W2, const float* __restrict__ b2,
                       float* __restrict__ out, int out_size)
{
    int e = blockIdx.x;
    int tid = threadIdx.x;
    int j = tid & 31, g = tid >> 5;
    const float* base = f3 + (size_t)e * 512 * 32;
    float acc = 0.f;
    for (int r = g; r < 512; r += 8) acc += base[r * 32 + j];
    __shared__ float red[8][32];
    red[g][j] = acc;
    __syncthreads();
    if (tid < 32) {
        float s = 0.f;
#pragma unroll
        for (int gg = 0; gg < 8; ++gg) s += red[gg][tid];
        float pooled = s * (1.f / 512.f);
        float h = b1[tid];
#pragma unroll
        for (int i = 0; i < 32; ++i)
            h = fmaf(__shfl_sync(0xffffffffu, pooled, i), W1[i * 32 + tid], h);
        h = eluf(h);
        float t = h * W2[tid];
#pragma unroll
        for (int o = 16; o; o >>= 1) t += __shfl_down_sync(0xffffffffu, t, o);
        if (tid == 0) {
            float prob = 1.f / (1.f + expf(-(t + b2[0])));
            out[e] = prob;
            if (out_size == 2 * BB) out[BB + e] = (float)e;
            else if (out_size == 3 * BB) ((long long*)(out + BB))[e] = (long long)e;
        }
    }
}

// ---------------- launch ------------------------------------------------------
extern "C" void kernel_launch(void* const* d_in, const int* in_sizes, int n_in,
                              void* d_out, int out_size)
{
    const float* x_sv   = (const float*)d_in[0];
    const float* x_trk  = (const float*)d_in[1];
    const float* x_pfc  = (const float*)d_in[2];
    const float* sv_W1  = (const float*)d_in[6];
    const float* sv_b1  = (const float*)d_in[7];
    const float* sv_W2  = (const float*)d_in[8];
    const float* sv_b2  = (const float*)d_in[9];
    const float* trk_W1 = (const float*)d_in[10];
    const float* trk_b1 = (const float*)d_in[11];
    const float* trk_W2 = (const float*)d_in[12];
    const float* trk_b2 = (const float*)d_in[13];
    const float* pfc_W1 = (const float*)d_in[14];
    const float* pfc_b1 = (const float*)d_in[15];
    const float* pfc_W2 = (const float*)d_in[16];
    const float* pfc_b2 = (const float*)d_in[17];
    const float* conv_W = (const float*)d_in[18];
    const float* conv_b = (const float*)d_in[19];
    const float* out_W1 = (const float*)d_in[20];
    const float* out_b1 = (const float*)d_in[21];
    const float* out_W2 = (const float*)d_in[22];
    const float* out_b2 = (const float*)d_in[23];
    float* out = (float*)d_out;

    float *sv, *trk, *pfc, *U, *V, *V1, *f1, *f2, *f3;
    cudaGetSymbolAddress((void**)&sv,  g_sv);
    cudaGetSymbolAddress((void**)&trk, g_trk);
    cudaGetSymbolAddress((void**)&pfc, g_pfc);
    cudaGetSymbolAddress((void**)&U,   g_U);
    cudaGetSymbolAddress((void**)&V,   g_V);
    cudaGetSymbolAddress((void**)&V1,  g_V1);
    cudaGetSymbolAddress((void**)&f1,  g_f1);
    cudaGetSymbolAddress((void**)&f2,  g_f2);
    cudaGetSymbolAddress((void**)&f3,  g_f3);

    cudaFuncSetAttribute(knn_k, cudaFuncAttributeMaxDynamicSharedMemorySize, 112 * 1024);

    size_t smem64  = (size_t)N_SV  * 132 + 512 * KNN * 4 + 512 * CAP * 8;
    size_t smem512 = (size_t)N_PFC * 132 + 512 * KNN * 4 + 512 * CAP * 8;

    encode_all_k<<<8704, 256>>>(x_sv, x_trk, x_pfc,
                                sv_W1, sv_b1, sv_W2, sv_b2,
                                trk_W1, trk_b1, trk_W2, trk_b2,
                                pfc_W1, pfc_b1, pfc_W2, pfc_b2,
                                sv, trk, pfc);
    lin_all_k<<<8704, 256>>>(sv, trk, pfc, V1, U, V, conv_W, conv_b);
    knn_k<<<BB, 256, smem64 >>>(sv,  trk, V1, U, f1, N_SV);
    knn_k<<<BB, 256, smem512>>>(pfc, trk, V,  U, f2, N_PFC);
    lin2_k<<<8192, 256>>>(f1, f2, V, U, conv_W, conv_b);
    knn_k<<<BB, 256, smem512>>>(f1, f2, V, U, f3, N_TRK);
    pool_k<<<BB, 256>>>(f3, out_W1, out_b1, out_W2, out_b2, out, out_size);
}